// round 4
// baseline (speedup 1.0000x reference)
#include <cuda_runtime.h>
#include <math.h>
#include <float.h>

// ---------------- problem constants ----------------
constexpr int SEQ   = 2048;
constexpr int HIDN  = 2048;
constexpr int NHEAD = 16;
constexpr int NKVH  = 8;
constexpr int HDIM  = 128;
constexpr int QKVN  = (NHEAD + 2 * NKVH) * HDIM;   // 4096
constexpr float EPSF  = 1e-6f;
constexpr float SCALE = 0.08838834764831845f;      // 128^-0.5

// ---------------- scratch (static device, no allocs) ----------------
__device__ float g_hn   [(size_t)SEQ * HIDN];            // 16 MB
__device__ float g_qkv  [(size_t)SEQ * QKVN];            // 32 MB
__device__ float g_scores[(size_t)NHEAD * SEQ * SEQ];    // 256 MB
__device__ float g_attn [(size_t)SEQ * NHEAD * HDIM];    // 16 MB
__device__ float g_cos  [(size_t)SEQ * (HDIM / 2)];
__device__ float g_sin  [(size_t)SEQ * (HDIM / 2)];

// ---------------- reductions ----------------
__device__ __forceinline__ float warp_sum(float v) {
    #pragma unroll
    for (int o = 16; o; o >>= 1) v += __shfl_xor_sync(0xffffffffu, v, o);
    return v;
}
__device__ __forceinline__ float warp_max(float v) {
    #pragma unroll
    for (int o = 16; o; o >>= 1) v = fmaxf(v, __shfl_xor_sync(0xffffffffu, v, o));
    return v;
}
template <int NT>
__device__ __forceinline__ float block_sum(float v) {
    __shared__ float sh[NT / 32];
    __syncthreads();                         // guard reuse
    v = warp_sum(v);
    int lane = threadIdx.x & 31, w = threadIdx.x >> 5;
    if (lane == 0) sh[w] = v;
    __syncthreads();
    if (w == 0) {
        float x = (lane < NT / 32) ? sh[lane] : 0.f;
        x = warp_sum(x);
        if (lane == 0) sh[0] = x;
    }
    __syncthreads();
    return sh[0];
}
template <int NT>
__device__ __forceinline__ float block_max(float v) {
    __shared__ float sh[NT / 32];
    __syncthreads();
    v = warp_max(v);
    int lane = threadIdx.x & 31, w = threadIdx.x >> 5;
    if (lane == 0) sh[w] = v;
    __syncthreads();
    if (w == 0) {
        float x = (lane < NT / 32) ? sh[lane] : -FLT_MAX;
        x = warp_max(x);
        if (lane == 0) sh[0] = x;
    }
    __syncthreads();
    return sh[0];
}

// ---------------- 1. RMSNorm(hidden) ----------------
__global__ void __launch_bounds__(256) k_rmsnorm_hidden(
    const float* __restrict__ x, const float* __restrict__ w)
{
    int row = blockIdx.x;
    const float* xr = x    + (size_t)row * HIDN;
    float*       yr = g_hn + (size_t)row * HIDN;
    float ss = 0.f;
    for (int i = threadIdx.x; i < HIDN; i += 256) { float v = xr[i]; ss = fmaf(v, v, ss); }
    ss = block_sum<256>(ss);
    float r = rsqrtf(ss * (1.f / HIDN) + EPSF);
    for (int i = threadIdx.x; i < HIDN; i += 256) yr[i] = xr[i] * r * w[i];
}

// ---------------- 2. RoPE cos/sin table ----------------
__global__ void k_rope_table(const int* __restrict__ positions)
{
    int idx = blockIdx.x * blockDim.x + threadIdx.x;
    if (idx >= SEQ * (HDIM / 2)) return;
    int s = idx / (HDIM / 2);
    int d = idx % (HDIM / 2);
    double inv = exp(-(double)d * (log(10000.0) / 64.0));
    double ph  = (double)positions[s] * inv;
    double sd, cd;
    sincos(ph, &sd, &cd);
    g_cos[idx] = (float)cd;
    g_sin[idx] = (float)sd;
}

// ---------------- shared SGEMM-NT body ----------------
// C[bm+i, bn+j] = alpha * sum_k A[(bm+i)*lda + k] * B[(bn+j)*ldb + k]
// 128x128 tile, BK=8, 256 threads, 8x8 per thread. K must be multiple of 8.
__device__ __forceinline__ void sgemm_nt_body(
    const float* __restrict__ A, const float* __restrict__ B, float* __restrict__ C,
    int lda, int ldb, int ldc, int K, float alpha, int bm, int bn)
{
    __shared__ float As[8][128];
    __shared__ float Bs[8][128];
    int tid  = threadIdx.x;
    int lrow = tid >> 1;            // 0..127
    int lcol = (tid & 1) << 2;      // 0 or 4
    int tr   = tid >> 4;            // 0..15
    int tc   = tid & 15;            // 0..15
    const float* Ap = A + (size_t)(bm + lrow) * lda + lcol;
    const float* Bp = B + (size_t)(bn + lrow) * ldb + lcol;

    float acc[8][8];
    #pragma unroll
    for (int i = 0; i < 8; i++)
        #pragma unroll
        for (int j = 0; j < 8; j++) acc[i][j] = 0.f;

    for (int k0 = 0; k0 < K; k0 += 8) {
        float4 av = *(const float4*)(Ap + k0);
        float4 bv = *(const float4*)(Bp + k0);
        As[lcol + 0][lrow] = av.x; As[lcol + 1][lrow] = av.y;
        As[lcol + 2][lrow] = av.z; As[lcol + 3][lrow] = av.w;
        Bs[lcol + 0][lrow] = bv.x; Bs[lcol + 1][lrow] = bv.y;
        Bs[lcol + 2][lrow] = bv.z; Bs[lcol + 3][lrow] = bv.w;
        __syncthreads();
        #pragma unroll
        for (int k = 0; k < 8; k++) {
            float4 a0 = *(const float4*)&As[k][tr * 8];
            float4 a1 = *(const float4*)&As[k][tr * 8 + 4];
            float4 b0 = *(const float4*)&Bs[k][tc * 8];
            float4 b1 = *(const float4*)&Bs[k][tc * 8 + 4];
            float ar[8] = {a0.x, a0.y, a0.z, a0.w, a1.x, a1.y, a1.z, a1.w};
            float br[8] = {b0.x, b0.y, b0.z, b0.w, b1.x, b1.y, b1.z, b1.w};
            #pragma unroll
            for (int i = 0; i < 8; i++)
                #pragma unroll
                for (int j = 0; j < 8; j++)
                    acc[i][j] = fmaf(ar[i], br[j], acc[i][j]);
        }
        __syncthreads();
    }
    #pragma unroll
    for (int i = 0; i < 8; i++) {
        float* Cr = C + (size_t)(bm + tr * 8 + i) * ldc + bn + tc * 8;
        #pragma unroll
        for (int j = 0; j < 8; j += 4) {
            float4 v = make_float4(alpha * acc[i][j + 0], alpha * acc[i][j + 1],
                                   alpha * acc[i][j + 2], alpha * acc[i][j + 3]);
            *(float4*)(Cr + j) = v;
        }
    }
}

// ---------------- 3. QKV GEMM: g_qkv = g_hn @ w_qkv^T ----------------
__global__ void __launch_bounds__(256) k_gemm_qkv(const float* __restrict__ w_qkv)
{
    sgemm_nt_body(g_hn, w_qkv, g_qkv, HIDN, HIDN, QKVN, HIDN, 1.f,
                  blockIdx.y * 128, blockIdx.x * 128);
}

// ---------------- 4. per-head q/k RMSNorm + RoPE (in place in g_qkv) ----------------
__global__ void k_qknorm_rope(const float* __restrict__ qw, const float* __restrict__ kw)
{
    int s    = blockIdx.x;
    int hidx = blockIdx.y;           // 0..23: 16 q heads then 8 k heads
    float* x;
    const float* w;
    if (hidx < NHEAD) { x = g_qkv + (size_t)s * QKVN + (size_t)hidx * HDIM; w = qw; }
    else              { x = g_qkv + (size_t)s * QKVN + (size_t)NHEAD * HDIM
                              + (size_t)(hidx - NHEAD) * HDIM;              w = kw; }
    int d = threadIdx.x;             // 128 threads
    float v  = x[d];
    float ss = block_sum<128>(v * v);
    float r  = rsqrtf(ss * (1.f / HDIM) + EPSF);
    float xn = v * r * w[d];
    __shared__ float sh[HDIM];
    sh[d] = xn;
    __syncthreads();
    if (d < 64) {
        float c  = g_cos[(size_t)s * 64 + d];
        float sn = g_sin[(size_t)s * 64 + d];
        float x1 = sh[d], x2 = sh[d + 64];
        x[d]      = x1 * c - x2 * sn;
        x[d + 64] = x2 * c + x1 * sn;
    }
}

// ---------------- 5. scores = scale * Q @ K^T, causal block skip ----------------
__global__ void __launch_bounds__(256) k_scores()
{
    if (blockIdx.x > blockIdx.y) return;   // fully above diagonal: never read
    int h = blockIdx.z;
    const float* A = g_qkv + (size_t)h * HDIM;                                   // q head h
    const float* B = g_qkv + (size_t)NHEAD * HDIM + (size_t)(h >> 1) * HDIM;     // k kv-head h/2
    float*       C = g_scores + (size_t)h * SEQ * SEQ;
    sgemm_nt_body(A, B, C, QKVN, QKVN, SEQ, HDIM, SCALE,
                  blockIdx.y * 128, blockIdx.x * 128);
}

// ---------------- 6. causal softmax (zeros above diagonal) ----------------
__global__ void __launch_bounds__(256) k_softmax()
{
    int row = blockIdx.x, h = blockIdx.y;
    float* p = g_scores + (size_t)h * SEQ * SEQ + (size_t)row * SEQ;
    int n   = row + 1;                  // valid columns 0..row
    int tid = threadIdx.x;
    float loc[8];
    float m = -FLT_MAX;
    #pragma unroll
    for (int j = 0; j < 8; j++) {
        int i = tid + j * 256;
        float v = (i < n) ? p[i] : -FLT_MAX;
        loc[j] = v;
        m = fmaxf(m, v);
    }
    m = block_max<256>(m);
    float sum = 0.f;
    #pragma unroll
    for (int j = 0; j < 8; j++) {
        int i = tid + j * 256;
        float e = (i < n) ? __expf(loc[j] - m) : 0.f;
        loc[j] = e;
        sum += e;
    }
    sum = block_sum<256>(sum);
    float rinv = 1.f / sum;
    #pragma unroll
    for (int j = 0; j < 8; j++) {
        int i = tid + j * 256;
        p[i] = loc[j] * rinv;           // zeros written above diagonal
    }
}

// ---------------- 7. PV: attn = P @ V (NN, K truncated per row block) ----------------
__global__ void __launch_bounds__(256) k_pv()
{
    int h = blockIdx.z;
    const float* A = g_scores + (size_t)h * SEQ * SEQ;
    const float* B = g_qkv + (size_t)(NHEAD + NKVH) * HDIM + (size_t)(h >> 1) * HDIM; // v
    float*       C = g_attn + (size_t)h * HDIM;
    int bm  = blockIdx.y * 128;
    __shared__ float As[8][128];
    __shared__ float Bs[8][128];
    int tid  = threadIdx.x;
    int lrow = tid >> 1,  lcol = (tid & 1) << 2;
    int brow = tid >> 5,  bcol = (tid & 31) << 2;
    int tr   = tid >> 4,  tc   = tid & 15;
    const float* Ap = A + (size_t)(bm + lrow) * SEQ + lcol;

    float acc[8][8];
    #pragma unroll
    for (int i = 0; i < 8; i++)
        #pragma unroll
        for (int j = 0; j < 8; j++) acc[i][j] = 0.f;

    int kend = bm + 128;                // causal: P is zero beyond row block end
    for (int k0 = 0; k0 < kend; k0 += 8) {
        float4 av = *(const float4*)(Ap + k0);
        float4 bv = *(const float4*)(B + (size_t)(k0 + brow) * QKVN + bcol);
        As[lcol + 0][lrow] = av.x; As[lcol + 1][lrow] = av.y;
        As[lcol + 2][lrow] = av.z; As[lcol + 3][lrow] = av.w;
        *(float4*)&Bs[brow][bcol] = bv;
        __syncthreads();
        #pragma unroll
        for (int k = 0; k < 8; k++) {
            float4 a0 = *(const float4*)&As[k][tr * 8];
            float4 a1 = *(const float4*)&As[k][tr * 8 + 4];
            float4 b0 = *(const float4*)&Bs[k][tc * 8];
            float4 b1 = *(const float4*)&Bs[k][tc * 8 + 4];
            float ar[8] = {a0.x, a0.y, a0.z, a0.w, a1.x, a1.y, a1.z, a1.w};
            float br[8] = {b0.x, b0.y, b0.z, b0.w, b1.x, b1.y, b1.z, b1.w};
            #pragma unroll
            for (int i = 0; i < 8; i++)
                #pragma unroll
                for (int j = 0; j < 8; j++)
                    acc[i][j] = fmaf(ar[i], br[j], acc[i][j]);
        }
        __syncthreads();
    }
    #pragma unroll
    for (int i = 0; i < 8; i++) {
        float* Cr = C + (size_t)(bm + tr * 8 + i) * (NHEAD * HDIM) + tc * 8;
        #pragma unroll
        for (int j = 0; j < 8; j += 4)
            *(float4*)(Cr + j) = make_float4(acc[i][j], acc[i][j + 1], acc[i][j + 2], acc[i][j + 3]);
    }
}

// ---------------- 8. O projection: out = attn @ w_o^T ----------------
__global__ void __launch_bounds__(256) k_gemm_oproj(
    const float* __restrict__ w_o, float* __restrict__ out)
{
    sgemm_nt_body(g_attn, w_o, out, NHEAD * HDIM, NHEAD * HDIM, HIDN,
                  NHEAD * HDIM, 1.f, blockIdx.y * 128, blockIdx.x * 128);
}

// ---------------- launch ----------------
extern "C" void kernel_launch(void* const* d_in, const int* in_sizes, int n_in,
                              void* d_out, int out_size)
{
    const int*   positions = (const int*)  d_in[0];
    const float* hidden    = (const float*)d_in[1];
    const float* ln_w      = (const float*)d_in[2];
    const float* w_qkv     = (const float*)d_in[3];
    const float* w_o       = (const float*)d_in[4];
    const float* q_norm_w  = (const float*)d_in[5];
    const float* k_norm_w  = (const float*)d_in[6];
    float*       out       = (float*)d_out;

    k_rmsnorm_hidden<<<SEQ, 256>>>(hidden, ln_w);
    k_rope_table<<<(SEQ * (HDIM / 2) + 255) / 256, 256>>>(positions);
    k_gemm_qkv<<<dim3(QKVN / 128, SEQ / 128), 256>>>(w_qkv);
    k_qknorm_rope<<<dim3(SEQ, NHEAD + NKVH), 128>>>(q_norm_w, k_norm_w);
    k_scores<<<dim3(SEQ / 128, SEQ / 128, NHEAD), 256>>>();
    k_softmax<<<dim3(SEQ, NHEAD), 256>>>();
    k_pv<<<dim3(1, SEQ / 128, NHEAD), 256>>>();
    k_gemm_oproj<<<dim3(HIDN / 128, SEQ / 128), 256>>>(w_o, out);
}